// round 4
// baseline (speedup 1.0000x reference)
#include <cuda_runtime.h>
#include <cstdint>

// Problem constants
#define BATCH 16
#define NTOK  8192
#define FIN   256
#define FOUT  256
#define EPSBN 1e-5f

// GEMM tiling: CTA 128x256, warp 64x64, 8 warps (2m x 4n)
#define BM 128
#define BN 256
#define BK 32
#define NCHUNK (FIN / BK)        // 8
#define STAGES 3
#define PADK 4
#define LDK (BK + PADK)          // 36 floats
#define STAGE_FLOATS ((BM + BN) * LDK)            // 13824
#define SMEM_ALLOC (STAGES * STAGE_FLOATS * 4)    // 165888 B

// device-global scratch (no allocations allowed)
__device__ float g_sum  [BATCH * FOUT];
__device__ float g_sumsq[BATCH * FOUT];
__device__ float g_scale[BATCH * FOUT];
__device__ float g_shift[BATCH * FOUT];

// ---------------------------------------------------------------------------
__device__ __forceinline__ uint32_t s2u(const void* p) {
    uint32_t a;
    asm("{ .reg .u64 t; cvta.to.shared.u64 t, %1; cvt.u32.u64 %0, t; }"
        : "=r"(a) : "l"(p));
    return a;
}
__device__ __forceinline__ void cp16(uint32_t saddr, const void* g) {
    asm volatile("cp.async.cg.shared.global [%0], [%1], 16;"
                 :: "r"(saddr), "l"(g));
}
__device__ __forceinline__ void mma_tf32(float* c, const uint32_t* a,
                                         const uint32_t* b) {
    asm volatile(
        "mma.sync.aligned.m16n8k8.row.col.f32.tf32.tf32.f32 "
        "{%0,%1,%2,%3}, {%4,%5,%6,%7}, {%8,%9}, {%0,%1,%2,%3};"
        : "+f"(c[0]), "+f"(c[1]), "+f"(c[2]), "+f"(c[3])
        : "r"(a[0]), "r"(a[1]), "r"(a[2]), "r"(a[3]), "r"(b[0]), "r"(b[1]));
}

// ---------------------------------------------------------------------------
__global__ void zero_stats_kernel() {
    int i = blockIdx.x * blockDim.x + threadIdx.x;
    if (i < BATCH * FOUT) { g_sum[i] = 0.0f; g_sumsq[i] = 0.0f; }
}

// ---------------------------------------------------------------------------
// Kernel 1: mma.sync tf32 GEMM  y = x @ W^T + b, fused column stats
// grid = BATCH * 64 (m-tiles), block = 256 (8 warps, 2m x 4n of 64x64 tiles)
// ---------------------------------------------------------------------------
__global__ __launch_bounds__(256, 1)
void gemm_mma_kernel(const float* __restrict__ x,
                     const float* __restrict__ W,
                     const float* __restrict__ bias,
                     float* __restrict__ y)
{
    extern __shared__ float smem[];
    const uint32_t smem_u = s2u(smem);

    const int tid  = threadIdx.x;
    const int wid  = tid >> 5;
    const int lane = tid & 31;
    const int g    = lane >> 2;          // 0..7
    const int t    = lane & 3;           // 0..3

    const int bx = blockIdx.x;
    const int mt = bx & 63;
    const int b  = bx >> 6;
    const int m0 = mt * BM;

    const float* xb = x + ((size_t)b * NTOK + m0) * FIN;

    const int warp_m = wid >> 2;         // 0..1 -> 64-row slice
    const int warp_n = wid & 3;          // 0..3 -> 64-col slice

    float acc[4][8][4];
#pragma unroll
    for (int mi = 0; mi < 4; mi++)
#pragma unroll
        for (int ni = 0; ni < 8; ni++)
#pragma unroll
            for (int i = 0; i < 4; i++) acc[mi][ni][i] = 0.0f;

    // stage loader: A[128][BK] + B[256][BK] as 16B cp.async granules
    const int lr = tid >> 3;        // 0..31
    const int lg = tid & 7;         // granule within row
    auto load_stage = [&](int c, int s) {
        const uint32_t abase = smem_u + (uint32_t)(s * STAGE_FLOATS) * 4u;
        const uint32_t bbase = abase + (uint32_t)(BM * LDK) * 4u;
        const int k0 = c * BK;
#pragma unroll
        for (int i = 0; i < 4; i++) {        // A: 128 rows
            int r = lr + i * 32;
            cp16(abase + (uint32_t)(r * LDK + lg * 4) * 4u,
                 xb + (size_t)r * FIN + k0 + lg * 4);
        }
#pragma unroll
        for (int i = 0; i < 8; i++) {        // B: 256 rows (all of W)
            int r = lr + i * 32;
            cp16(bbase + (uint32_t)(r * LDK + lg * 4) * 4u,
                 W + (size_t)r * FIN + k0 + lg * 4);
        }
    };

    // prologue: 2 stages in flight
    load_stage(0, 0);
    asm volatile("cp.async.commit_group;" ::: "memory");
    load_stage(1, 1);
    asm volatile("cp.async.commit_group;" ::: "memory");

    // mainloop: one barrier per chunk
    for (int c = 0; c < NCHUNK; c++) {
        if (c + 1 < NCHUNK)
            asm volatile("cp.async.wait_group 1;" ::: "memory");
        else
            asm volatile("cp.async.wait_group 0;" ::: "memory");
        __syncthreads();

        if (c + 2 < NCHUNK) {
            load_stage(c + 2, (c + 2) % STAGES);
            asm volatile("cp.async.commit_group;" ::: "memory");
        }

        const float* As = smem + (c % STAGES) * STAGE_FLOATS
                          + (warp_m * 64) * LDK;
        const float* Bs = smem + (c % STAGES) * STAGE_FLOATS + BM * LDK
                          + (warp_n * 64) * LDK;

#pragma unroll
        for (int ks = 0; ks < 4; ks++) {
            const int kk = ks * 8;
            uint32_t af[4][4];
#pragma unroll
            for (int mi = 0; mi < 4; mi++) {
                int r = mi * 16 + g;
                af[mi][0] = __float_as_uint(As[ r      * LDK + kk + t    ]);
                af[mi][1] = __float_as_uint(As[(r + 8) * LDK + kk + t    ]);
                af[mi][2] = __float_as_uint(As[ r      * LDK + kk + t + 4]);
                af[mi][3] = __float_as_uint(As[(r + 8) * LDK + kk + t + 4]);
            }
            uint32_t bf[8][2];
#pragma unroll
            for (int ni = 0; ni < 8; ni++) {
                int n = ni * 8 + g;
                bf[ni][0] = __float_as_uint(Bs[n * LDK + kk + t    ]);
                bf[ni][1] = __float_as_uint(Bs[n * LDK + kk + t + 4]);
            }
#pragma unroll
            for (int mi = 0; mi < 4; mi++)
#pragma unroll
                for (int ni = 0; ni < 8; ni++)
                    mma_tf32(acc[mi][ni], af[mi], bf[ni]);
        }
    }

    // ---------------- epilogue: bias + y store + column stats ----------------
    __syncthreads();
    float* psum = smem;            // [256]
    float* psq  = smem + 256;      // [256]
    if (tid < 256) { psum[tid] = 0.0f; psq[tid] = 0.0f; }
    __syncthreads();

    float* ybase = y + ((size_t)b * NTOK + m0) * FOUT;
    const int rA0 = warp_m * 64 + g;

#pragma unroll
    for (int ni = 0; ni < 8; ni++) {
        const int cc = warp_n * 64 + ni * 8 + 2 * t;
        const float b0v = __ldg(&bias[cc]);
        const float b1v = __ldg(&bias[cc + 1]);
        float s0 = 0.f, s1 = 0.f, q0 = 0.f, q1 = 0.f;
#pragma unroll
        for (int mi = 0; mi < 4; mi++) {
            int r = rA0 + mi * 16;
            float v0 = acc[mi][ni][0] + b0v;
            float v1 = acc[mi][ni][1] + b1v;
            float v2 = acc[mi][ni][2] + b0v;
            float v3 = acc[mi][ni][3] + b1v;
            *(float2*)(ybase + (size_t)r * FOUT + cc)       = make_float2(v0, v1);
            *(float2*)(ybase + (size_t)(r + 8) * FOUT + cc) = make_float2(v2, v3);
            s0 += v0 + v2;  s1 += v1 + v3;
            q0 += v0 * v0 + v2 * v2;
            q1 += v1 * v1 + v3 * v3;
        }
        // reduce over the 8 row-groups (lane bits [2:4])
#pragma unroll
        for (int m = 4; m <= 16; m <<= 1) {
            s0 += __shfl_xor_sync(0xFFFFFFFF, s0, m);
            s1 += __shfl_xor_sync(0xFFFFFFFF, s1, m);
            q0 += __shfl_xor_sync(0xFFFFFFFF, q0, m);
            q1 += __shfl_xor_sync(0xFFFFFFFF, q1, m);
        }
        if (lane < 4) {                       // g == 0 lanes hold totals
            atomicAdd(&psum[cc], s0);  atomicAdd(&psum[cc + 1], s1);
            atomicAdd(&psq [cc], q0);  atomicAdd(&psq [cc + 1], q1);
        }
    }
    __syncthreads();
    if (tid < 256) {
        atomicAdd(&g_sum  [b * FOUT + tid], psum[tid]);
        atomicAdd(&g_sumsq[b * FOUT + tid], psq [tid]);
    }
}

// ---------------------------------------------------------------------------
__global__ void finalize_stats_kernel(const float* __restrict__ gamma,
                                      const float* __restrict__ beta)
{
    int i = blockIdx.x * blockDim.x + threadIdx.x;
    if (i >= BATCH * FOUT) return;
    int o = i & (FOUT - 1);
    float invN = 1.0f / (float)NTOK;
    float mean = g_sum[i] * invN;
    float var  = fmaxf(g_sumsq[i] * invN - mean * mean, 0.0f);
    float sc   = gamma[o] * rsqrtf(var + EPSBN);
    g_scale[i] = sc;
    g_shift[i] = beta[o] - mean * sc;
}

// ---------------------------------------------------------------------------
// Kernel 3: in-place normalize (float4), reverse order for L2 hits on the
// most-recently-written portion of y
// ---------------------------------------------------------------------------
__global__ void normalize_kernel(float* __restrict__ y)
{
    size_t i4 = (size_t)(gridDim.x - 1 - blockIdx.x) * blockDim.x + threadIdx.x;
    const size_t total4 = (size_t)BATCH * NTOK * FOUT / 4;
    if (i4 >= total4) return;
    size_t e = i4 * 4;
    int o  = (int)(e & (FOUT - 1));
    int bb = (int)(e >> 21);
    const float4 sc = *reinterpret_cast<const float4*>(&g_scale[bb * FOUT + o]);
    const float4 sh = *reinterpret_cast<const float4*>(&g_shift[bb * FOUT + o]);
    float4 v = reinterpret_cast<float4*>(y)[i4];
    v.x = v.x * sc.x + sh.x;
    v.y = v.y * sc.y + sh.y;
    v.z = v.z * sc.z + sh.z;
    v.w = v.w * sc.w + sh.w;
    reinterpret_cast<float4*>(y)[i4] = v;
}

// ---------------------------------------------------------------------------
extern "C" void kernel_launch(void* const* d_in, const int* in_sizes, int n_in,
                              void* d_out, int out_size)
{
    const float* x     = (const float*)d_in[0];
    const float* W     = (const float*)d_in[1];
    const float* bias  = (const float*)d_in[2];
    const float* gamma = (const float*)d_in[3];
    const float* beta  = (const float*)d_in[4];
    float* out = (float*)d_out;

    cudaFuncSetAttribute(gemm_mma_kernel,
                         cudaFuncAttributeMaxDynamicSharedMemorySize,
                         SMEM_ALLOC);

    zero_stats_kernel<<<(BATCH * FOUT + 255) / 256, 256>>>();

    gemm_mma_kernel<<<BATCH * 64, 256, SMEM_ALLOC>>>(x, W, bias, out);

    finalize_stats_kernel<<<(BATCH * FOUT + 255) / 256, 256>>>(gamma, beta);

    size_t total4 = (size_t)BATCH * NTOK * FOUT / 4;
    normalize_kernel<<<(unsigned)((total4 + 255) / 256), 256>>>(out);
}

// round 6
// speedup vs baseline: 1.0342x; 1.0342x over previous
#include <cuda_runtime.h>
#include <cuda_fp16.h>
#include <cstdint>

// Problem constants
#define BATCH 16
#define NTOK  8192
#define FIN   256
#define FOUT  256
#define EPSBN 1e-5f

// GEMM tiling: CTA 128x256, warp 64x64, 8 warps (2m x 4n), fp16 MMA
#define BM 128
#define BN 256
#define BK 32
#define NCHUNK (FIN / BK)        // 8
#define STAGES 3
#define LDK  36                  // fp32 stage row stride (floats)
#define LDKH 40                  // fp16 tile row stride (halves) -> conflict-free
#define STAGE_FLOATS ((BM + BN) * LDK)            // 13824
#define FP32_BYTES  (STAGES * STAGE_FLOATS * 4)   // 165888
#define AH_HALVES   (BM * LDKH)                   // 5120
#define BH_HALVES   (BN * LDKH)                   // 10240
#define SMEM_ALLOC  (FP32_BYTES + (AH_HALVES + BH_HALVES) * 2)   // 196608

// device-global scratch (no allocations allowed)
__device__ float g_sum  [BATCH * FOUT];
__device__ float g_sumsq[BATCH * FOUT];
__device__ float g_scale[BATCH * FOUT];
__device__ float g_shift[BATCH * FOUT];

// ---------------------------------------------------------------------------
__device__ __forceinline__ uint32_t s2u(const void* p) {
    uint32_t a;
    asm("{ .reg .u64 t; cvta.to.shared.u64 t, %1; cvt.u32.u64 %0, t; }"
        : "=r"(a) : "l"(p));
    return a;
}
__device__ __forceinline__ void cp16(uint32_t saddr, const void* g) {
    asm volatile("cp.async.cg.shared.global [%0], [%1], 16;"
                 :: "r"(saddr), "l"(g));
}
__device__ __forceinline__ void mma_f16(float* c, const uint32_t* a,
                                        const uint32_t* b) {
    asm volatile(
        "mma.sync.aligned.m16n8k16.row.col.f32.f16.f16.f32 "
        "{%0,%1,%2,%3}, {%4,%5,%6,%7}, {%8,%9}, {%0,%1,%2,%3};"
        : "+f"(c[0]), "+f"(c[1]), "+f"(c[2]), "+f"(c[3])
        : "r"(a[0]), "r"(a[1]), "r"(a[2]), "r"(a[3]), "r"(b[0]), "r"(b[1]));
}

// ---------------------------------------------------------------------------
__global__ void zero_stats_kernel() {
    int i = blockIdx.x * blockDim.x + threadIdx.x;
    if (i < BATCH * FOUT) { g_sum[i] = 0.0f; g_sumsq[i] = 0.0f; }
}

// ---------------------------------------------------------------------------
// Kernel 1: fp16 mma.sync GEMM  y = x @ W^T + b, fused column stats.
// fp32 tiles arrive via cp.async; converted in-kernel to fp16 smem tiles.
// grid = BATCH * 64 (m-tiles), block = 256 (8 warps, 2m x 4n of 64x64)
// ---------------------------------------------------------------------------
__global__ __launch_bounds__(256, 1)
void gemm_mma_kernel(const float* __restrict__ x,
                     const float* __restrict__ W,
                     const float* __restrict__ bias,
                     float* __restrict__ y)
{
    extern __shared__ float smem[];
    const uint32_t smem_u = s2u(smem);
    __half* Ah = (__half*)((char*)smem + FP32_BYTES);
    __half* Bh = Ah + AH_HALVES;

    const int tid  = threadIdx.x;
    const int wid  = tid >> 5;
    const int lane = tid & 31;
    const int g    = lane >> 2;          // 0..7
    const int t    = lane & 3;           // 0..3

    const int bx = blockIdx.x;
    const int mt = bx & 63;
    const int b  = bx >> 6;
    const int m0 = mt * BM;

    const float* xb = x + ((size_t)b * NTOK + m0) * FIN;

    const int warp_m = wid >> 2;         // 0..1 -> 64-row slice
    const int warp_n = wid & 3;          // 0..3 -> 64-col slice

    float acc[4][8][4];
#pragma unroll
    for (int mi = 0; mi < 4; mi++)
#pragma unroll
        for (int ni = 0; ni < 8; ni++)
#pragma unroll
            for (int i = 0; i < 4; i++) acc[mi][ni][i] = 0.0f;

    // fp32 stage loader: A[128][BK] + B[256][BK] as 16B cp.async granules
    const int lr = tid >> 3;        // 0..31
    const int lg = tid & 7;         // granule within row
    auto load_stage = [&](int c, int s) {
        const uint32_t abase = smem_u + (uint32_t)(s * STAGE_FLOATS) * 4u;
        const uint32_t bbase = abase + (uint32_t)(BM * LDK) * 4u;
        const int k0 = c * BK;
#pragma unroll
        for (int i = 0; i < 4; i++) {        // A: 128 rows
            int r = lr + i * 32;
            cp16(abase + (uint32_t)(r * LDK + lg * 4) * 4u,
                 xb + (size_t)r * FIN + k0 + lg * 4);
        }
#pragma unroll
        for (int i = 0; i < 8; i++) {        // B: 256 rows (all of W)
            int r = lr + i * 32;
            cp16(bbase + (uint32_t)(r * LDK + lg * 4) * 4u,
                 W + (size_t)r * FIN + k0 + lg * 4);
        }
    };

    // prologue: 2 stages in flight
    load_stage(0, 0);
    asm volatile("cp.async.commit_group;" ::: "memory");
    load_stage(1, 1);
    asm volatile("cp.async.commit_group;" ::: "memory");

    // mainloop
    for (int c = 0; c < NCHUNK; c++) {
        if (c + 1 < NCHUNK)
            asm volatile("cp.async.wait_group 1;" ::: "memory");
        else
            asm volatile("cp.async.wait_group 0;" ::: "memory");
        __syncthreads();   // fp32 stage c visible; fp16 tiles free (prev mma done)

        // keep DRAM busy: issue next stage before converting
        if (c + 2 < NCHUNK) {
            load_stage(c + 2, (c + 2) % STAGES);
            asm volatile("cp.async.commit_group;" ::: "memory");
        }

        // convert fp32 stage -> fp16 tiles
        {
            const float* Sa = smem + (c % STAGES) * STAGE_FLOATS;
            const float* Sb = Sa + BM * LDK;
#pragma unroll
            for (int i = 0; i < 4; i++) {          // A: 1024 float4
                int idx = tid + i * 256;
                int r = idx >> 3, c4 = idx & 7;
                float4 v = *(const float4*)(Sa + r * LDK + c4 * 4);
                __half2 h0 = __floats2half2_rn(v.x, v.y);
                __half2 h1 = __floats2half2_rn(v.z, v.w);
                uint2 pk = make_uint2(*(uint32_t*)&h0, *(uint32_t*)&h1);
                *(uint2*)(Ah + r * LDKH + c4 * 4) = pk;
            }
#pragma unroll
            for (int i = 0; i < 8; i++) {          // B: 2048 float4
                int idx = tid + i * 256;
                int r = idx >> 3, c4 = idx & 7;
                float4 v = *(const float4*)(Sb + r * LDK + c4 * 4);
                __half2 h0 = __floats2half2_rn(v.x, v.y);
                __half2 h1 = __floats2half2_rn(v.z, v.w);
                uint2 pk = make_uint2(*(uint32_t*)&h0, *(uint32_t*)&h1);
                *(uint2*)(Bh + r * LDKH + c4 * 4) = pk;
            }
        }
        __syncthreads();   // fp16 tiles populated

        const __half* Aw = Ah + (warp_m * 64) * LDKH;
        const __half* Bw = Bh + (warp_n * 64) * LDKH;
#pragma unroll
        for (int ks = 0; ks < 2; ks++) {
            const int kk = ks * 16;
            uint32_t af[4][4];
#pragma unroll
            for (int mi = 0; mi < 4; mi++) {
                int r = mi * 16 + g;
                af[mi][0] = *(const uint32_t*)&Aw[ r      * LDKH + kk + 2 * t    ];
                af[mi][1] = *(const uint32_t*)&Aw[(r + 8) * LDKH + kk + 2 * t    ];
                af[mi][2] = *(const uint32_t*)&Aw[ r      * LDKH + kk + 2 * t + 8];
                af[mi][3] = *(const uint32_t*)&Aw[(r + 8) * LDKH + kk + 2 * t + 8];
            }
            uint32_t bf[8][2];
#pragma unroll
            for (int ni = 0; ni < 8; ni++) {
                int n = ni * 8 + g;
                bf[ni][0] = *(const uint32_t*)&Bw[n * LDKH + kk + 2 * t    ];
                bf[ni][1] = *(const uint32_t*)&Bw[n * LDKH + kk + 2 * t + 8];
            }
#pragma unroll
            for (int mi = 0; mi < 4; mi++)
#pragma unroll
                for (int ni = 0; ni < 8; ni++)
                    mma_f16(acc[mi][ni], af[mi], bf[ni]);
        }
    }

    // ---------------- epilogue: bias + y store + column stats ----------------
    __syncthreads();
    float* psum = smem;            // [256]
    float* psq  = smem + 256;      // [256]
    if (tid < 256) { psum[tid] = 0.0f; psq[tid] = 0.0f; }
    __syncthreads();

    float* ybase = y + ((size_t)b * NTOK + m0) * FOUT;
    const int rA0 = warp_m * 64 + g;

#pragma unroll
    for (int ni = 0; ni < 8; ni++) {
        const int cc = warp_n * 64 + ni * 8 + 2 * t;
        const float b0v = __ldg(&bias[cc]);
        const float b1v = __ldg(&bias[cc + 1]);
        float s0 = 0.f, s1 = 0.f, q0 = 0.f, q1 = 0.f;
#pragma unroll
        for (int mi = 0; mi < 4; mi++) {
            int r = rA0 + mi * 16;
            float v0 = acc[mi][ni][0] + b0v;
            float v1 = acc[mi][ni][1] + b1v;
            float v2 = acc[mi][ni][2] + b0v;
            float v3 = acc[mi][ni][3] + b1v;
            *(float2*)(ybase + (size_t)r * FOUT + cc)       = make_float2(v0, v1);
            *(float2*)(ybase + (size_t)(r + 8) * FOUT + cc) = make_float2(v2, v3);
            s0 += v0 + v2;  s1 += v1 + v3;
            q0 += v0 * v0 + v2 * v2;
            q1 += v1 * v1 + v3 * v3;
        }
#pragma unroll
        for (int m = 4; m <= 16; m <<= 1) {
            s0 += __shfl_xor_sync(0xFFFFFFFF, s0, m);
            s1 += __shfl_xor_sync(0xFFFFFFFF, s1, m);
            q0 += __shfl_xor_sync(0xFFFFFFFF, q0, m);
            q1 += __shfl_xor_sync(0xFFFFFFFF, q1, m);
        }
        if (lane < 4) {
            atomicAdd(&psum[cc], s0);  atomicAdd(&psum[cc + 1], s1);
            atomicAdd(&psq [cc], q0);  atomicAdd(&psq [cc + 1], q1);
        }
    }
    __syncthreads();
    if (tid < 256) {
        atomicAdd(&g_sum  [b * FOUT + tid], psum[tid]);
        atomicAdd(&g_sumsq[b * FOUT + tid], psq [tid]);
    }
}

// ---------------------------------------------------------------------------
__global__ void finalize_stats_kernel(const float* __restrict__ gamma,
                                      const float* __restrict__ beta)
{
    int i = blockIdx.x * blockDim.x + threadIdx.x;
    if (i >= BATCH * FOUT) return;
    int o = i & (FOUT - 1);
    float invN = 1.0f / (float)NTOK;
    float mean = g_sum[i] * invN;
    float var  = fmaxf(g_sumsq[i] * invN - mean * mean, 0.0f);
    float sc   = gamma[o] * rsqrtf(var + EPSBN);
    g_scale[i] = sc;
    g_shift[i] = beta[o] - mean * sc;
}

// ---------------------------------------------------------------------------
__global__ void normalize_kernel(float* __restrict__ y)
{
    size_t i4 = (size_t)(gridDim.x - 1 - blockIdx.x) * blockDim.x + threadIdx.x;
    const size_t total4 = (size_t)BATCH * NTOK * FOUT / 4;
    if (i4 >= total4) return;
    size_t e = i4 * 4;
    int o  = (int)(e & (FOUT - 1));
    int bb = (int)(e >> 21);
    const float4 sc = *reinterpret_cast<const float4*>(&g_scale[bb * FOUT + o]);
    const float4 sh = *reinterpret_cast<const float4*>(&g_shift[bb * FOUT + o]);
    float4 v = reinterpret_cast<float4*>(y)[i4];
    v.x = v.x * sc.x + sh.x;
    v.y = v.y * sc.y + sh.y;
    v.z = v.z * sc.z + sh.z;
    v.w = v.w * sc.w + sh.w;
    reinterpret_cast<float4*>(y)[i4] = v;
}

// ---------------------------------------------------------------------------
extern "C" void kernel_launch(void* const* d_in, const int* in_sizes, int n_in,
                              void* d_out, int out_size)
{
    const float* x     = (const float*)d_in[0];
    const float* W     = (const float*)d_in[1];
    const float* bias  = (const float*)d_in[2];
    const float* gamma = (const float*)d_in[3];
    const float* beta  = (const float*)d_in[4];
    float* out = (float*)d_out;

    cudaFuncSetAttribute(gemm_mma_kernel,
                         cudaFuncAttributeMaxDynamicSharedMemorySize,
                         SMEM_ALLOC);

    zero_stats_kernel<<<(BATCH * FOUT + 255) / 256, 256>>>();

    gemm_mma_kernel<<<BATCH * 64, 256, SMEM_ALLOC>>>(x, W, bias, out);

    finalize_stats_kernel<<<(BATCH * FOUT + 255) / 256, 256>>>(gamma, beta);

    size_t total4 = (size_t)BATCH * NTOK * FOUT / 4;
    normalize_kernel<<<(unsigned)((total4 + 255) / 256), 256>>>(out);
}

// round 7
// speedup vs baseline: 1.1307x; 1.0933x over previous
#include <cuda_runtime.h>
#include <cuda_fp16.h>
#include <cstdint>

// Problem constants
#define BATCH 16
#define NTOK  8192
#define FIN   256
#define FOUT  256
#define EPSBN 1e-5f
#define CTAS_PER_BATCH 64        // NTOK / BM

// GEMM tiling: CTA 128x256, warp 64x64, 8 warps (2m x 4n), fp16 MMA
#define BM 128
#define BN 256
#define BK 32
#define NCHUNK (FIN / BK)        // 8
#define STAGES 3
#define LDA32 36                 // fp32 A stage row stride (floats)
#define LDKH  40                 // fp16 row stride (halves)
// stage = A fp32 [128][36] + B fp16 [256][40]
#define A_STAGE_BYTES (BM * LDA32 * 4)            // 18432
#define B_STAGE_BYTES (BN * LDKH * 2)             // 20480
#define STAGE_BYTES   (A_STAGE_BYTES + B_STAGE_BYTES)   // 38912
#define AH_BYTES      (BM * LDKH * 2)             // 10240
#define SMEM_ALLOC    (STAGES * STAGE_BYTES + AH_BYTES) // 126976

// device-global scratch (no allocations allowed)
__device__ __half g_Wh  [FOUT * FIN];
__device__ float  g_sum  [BATCH * FOUT];
__device__ float  g_sumsq[BATCH * FOUT];
__device__ int    g_count[BATCH];

// ---------------------------------------------------------------------------
__device__ __forceinline__ uint32_t s2u(const void* p) {
    uint32_t a;
    asm("{ .reg .u64 t; cvta.to.shared.u64 t, %1; cvt.u32.u64 %0, t; }"
        : "=r"(a) : "l"(p));
    return a;
}
__device__ __forceinline__ void cp16(uint32_t saddr, const void* g) {
    asm volatile("cp.async.cg.shared.global [%0], [%1], 16;"
                 :: "r"(saddr), "l"(g));
}
__device__ __forceinline__ void mma_f16(float* c, const uint32_t* a,
                                        const uint32_t* b) {
    asm volatile(
        "mma.sync.aligned.m16n8k16.row.col.f32.f16.f16.f32 "
        "{%0,%1,%2,%3}, {%4,%5,%6,%7}, {%8,%9}, {%0,%1,%2,%3};"
        : "+f"(c[0]), "+f"(c[1]), "+f"(c[2]), "+f"(c[3])
        : "r"(a[0]), "r"(a[1]), "r"(a[2]), "r"(a[3]), "r"(b[0]), "r"(b[1]));
}

// ---------------------------------------------------------------------------
// Kernel A: W fp32 -> fp16 (once per call; 128 blocks x 256 threads)
// ---------------------------------------------------------------------------
__global__ void wconv_kernel(const float* __restrict__ W) {
    int i = blockIdx.x * blockDim.x + threadIdx.x;      // half2 index
    if (i < FOUT * FIN / 2) {
        float2 f = reinterpret_cast<const float2*>(W)[i];
        reinterpret_cast<__half2*>(g_Wh)[i] = __floats2half2_rn(f.x, f.y);
    }
}

// ---------------------------------------------------------------------------
// Kernel B: zero stats + counters
// ---------------------------------------------------------------------------
__global__ void zero_stats_kernel() {
    int i = blockIdx.x * blockDim.x + threadIdx.x;
    if (i < BATCH * FOUT) { g_sum[i] = 0.0f; g_sumsq[i] = 0.0f; }
    if (i < BATCH) g_count[i] = 0;
}

// ---------------------------------------------------------------------------
// Kernel C: fused GEMM + BatchNorm.
//  - fp16 mma.sync GEMM (x converted in-kernel, W pre-converted)
//  - column stats via shfl + global atomics
//  - per-batch spin barrier, then normalized output written from registers
// grid = BATCH * 64 (batch = bx>>6 contiguous!), block = 256
// ---------------------------------------------------------------------------
__global__ __launch_bounds__(256, 1)
void gemm_bn_kernel(const float* __restrict__ x,
                    const float* __restrict__ bias,
                    const float* __restrict__ gamma,
                    const float* __restrict__ beta,
                    float* __restrict__ out)
{
    extern __shared__ char smem[];
    const uint32_t smem_u = s2u(smem);
    __half* Ah = (__half*)(smem + STAGES * STAGE_BYTES);

    const int tid  = threadIdx.x;
    const int lane = tid & 31;
    const int wid  = tid >> 5;
    const int g    = lane >> 2;          // 0..7
    const int t    = lane & 3;           // 0..3

    const int bx = blockIdx.x;
    const int mt = bx & 63;
    const int b  = bx >> 6;
    const int m0 = mt * BM;

    const float* xb = x + ((size_t)b * NTOK + m0) * FIN;

    const int warp_m = wid >> 2;         // 0..1 -> 64-row slice
    const int warp_n = wid & 3;          // 0..3 -> 64-col slice

    float acc[4][8][4];
#pragma unroll
    for (int mi = 0; mi < 4; mi++)
#pragma unroll
        for (int ni = 0; ni < 8; ni++)
#pragma unroll
            for (int i = 0; i < 4; i++) acc[mi][ni][i] = 0.0f;

    // stage loader: A fp32 (1024 x 16B) + B fp16 (1024 x 16B)
    auto load_stage = [&](int c, int s) {
        const uint32_t abase = smem_u + (uint32_t)(s * STAGE_BYTES);
        const uint32_t bbase = abase + A_STAGE_BYTES;
        const int k0 = c * BK;
#pragma unroll
        for (int i = 0; i < 4; i++) {        // A: 128 rows x 8 granules
            int idx = tid + i * 256;
            int r = idx >> 3, gi = idx & 7;
            cp16(abase + (uint32_t)(r * LDA32 + gi * 4) * 4u,
                 xb + (size_t)r * FIN + k0 + gi * 4);
        }
#pragma unroll
        for (int i = 0; i < 4; i++) {        // B: 256 rows x 4 granules (fp16)
            int idx = tid + i * 256;
            int r = idx >> 2, gi = idx & 3;
            cp16(bbase + (uint32_t)(r * LDKH + gi * 8) * 2u,
                 g_Wh + (size_t)r * FIN + k0 + gi * 8);
        }
    };

    load_stage(0, 0);
    asm volatile("cp.async.commit_group;" ::: "memory");
    load_stage(1, 1);
    asm volatile("cp.async.commit_group;" ::: "memory");

    for (int c = 0; c < NCHUNK; c++) {
        if (c + 1 < NCHUNK)
            asm volatile("cp.async.wait_group 1;" ::: "memory");
        else
            asm volatile("cp.async.wait_group 0;" ::: "memory");
        __syncthreads();   // stage c visible; Ah free (prev MMA done)

        if (c + 2 < NCHUNK) {
            load_stage(c + 2, (c + 2) % STAGES);
            asm volatile("cp.async.commit_group;" ::: "memory");
        }

        // convert A fp32 stage -> fp16 tile
        {
            const float* Sa = (const float*)(smem + (c % STAGES) * STAGE_BYTES);
#pragma unroll
            for (int i = 0; i < 4; i++) {
                int idx = tid + i * 256;
                int r = idx >> 3, c4 = idx & 7;
                float4 v = *(const float4*)(Sa + r * LDA32 + c4 * 4);
                __half2 h0 = __floats2half2_rn(v.x, v.y);
                __half2 h1 = __floats2half2_rn(v.z, v.w);
                uint2 pk = make_uint2(*(uint32_t*)&h0, *(uint32_t*)&h1);
                *(uint2*)(Ah + r * LDKH + c4 * 4) = pk;
            }
        }
        __syncthreads();

        const __half* Aw = Ah + (warp_m * 64) * LDKH;
        const __half* Bw = (const __half*)(smem + (c % STAGES) * STAGE_BYTES
                             + A_STAGE_BYTES) + (warp_n * 64) * LDKH;
#pragma unroll
        for (int ks = 0; ks < 2; ks++) {
            const int kk = ks * 16;
            uint32_t af[4][4];
#pragma unroll
            for (int mi = 0; mi < 4; mi++) {
                int r = mi * 16 + g;
                af[mi][0] = *(const uint32_t*)&Aw[ r      * LDKH + kk + 2 * t    ];
                af[mi][1] = *(const uint32_t*)&Aw[(r + 8) * LDKH + kk + 2 * t    ];
                af[mi][2] = *(const uint32_t*)&Aw[ r      * LDKH + kk + 2 * t + 8];
                af[mi][3] = *(const uint32_t*)&Aw[(r + 8) * LDKH + kk + 2 * t + 8];
            }
            uint32_t bf[8][2];
#pragma unroll
            for (int ni = 0; ni < 8; ni++) {
                int n = ni * 8 + g;
                bf[ni][0] = *(const uint32_t*)&Bw[n * LDKH + kk + 2 * t    ];
                bf[ni][1] = *(const uint32_t*)&Bw[n * LDKH + kk + 2 * t + 8];
            }
#pragma unroll
            for (int mi = 0; mi < 4; mi++)
#pragma unroll
                for (int ni = 0; ni < 8; ni++)
                    mma_f16(acc[mi][ni], af[mi], bf[ni]);
        }
    }

    // ---------------- stats: column sums/sumsq -> global atomics -------------
    float* gs = &g_sum  [b * FOUT];
    float* gq = &g_sumsq[b * FOUT];
#pragma unroll
    for (int ni = 0; ni < 8; ni++) {
        const int cc = warp_n * 64 + ni * 8 + 2 * t;
        const float b0v = __ldg(&bias[cc]);
        const float b1v = __ldg(&bias[cc + 1]);
        float s0 = 0.f, s1 = 0.f, q0 = 0.f, q1 = 0.f;
#pragma unroll
        for (int mi = 0; mi < 4; mi++) {
            float v0 = acc[mi][ni][0] + b0v;
            float v1 = acc[mi][ni][1] + b1v;
            float v2 = acc[mi][ni][2] + b0v;
            float v3 = acc[mi][ni][3] + b1v;
            s0 += v0 + v2;  s1 += v1 + v3;
            q0 += v0 * v0 + v2 * v2;
            q1 += v1 * v1 + v3 * v3;
        }
#pragma unroll
        for (int m = 4; m <= 16; m <<= 1) {
            s0 += __shfl_xor_sync(0xFFFFFFFF, s0, m);
            s1 += __shfl_xor_sync(0xFFFFFFFF, s1, m);
            q0 += __shfl_xor_sync(0xFFFFFFFF, q0, m);
            q1 += __shfl_xor_sync(0xFFFFFFFF, q1, m);
        }
        if (lane < 4) {       // g==0 lanes hold 64-row totals for this warp
            atomicAdd(&gs[cc], s0);  atomicAdd(&gs[cc + 1], s1);
            atomicAdd(&gq[cc], q0);  atomicAdd(&gq[cc + 1], q1);
        }
    }

    // ---------------- per-batch spin barrier ---------------------------------
    __threadfence();            // make this CTA's atomics visible
    __syncthreads();
    if (tid == 0) {
        atomicAdd(&g_count[b], 1);
        while (atomicAdd(&g_count[b], 0) < CTAS_PER_BATCH)
            __nanosleep(100);
    }
    __syncthreads();
    __threadfence();

    // ---------------- normalize from registers, write final output -----------
    const float invN = 1.0f / (float)NTOK;
    float* obase = out + ((size_t)b * NTOK + m0) * FOUT;
    const int rA0 = warp_m * 64 + g;

#pragma unroll
    for (int ni = 0; ni < 8; ni++) {
        const int cc = warp_n * 64 + ni * 8 + 2 * t;
        const float b0v = __ldg(&bias[cc]);
        const float b1v = __ldg(&bias[cc + 1]);
        float mean0 = __ldcg(&gs[cc])     * invN;
        float mean1 = __ldcg(&gs[cc + 1]) * invN;
        float var0  = fmaxf(__ldcg(&gq[cc])     * invN - mean0 * mean0, 0.0f);
        float var1  = fmaxf(__ldcg(&gq[cc + 1]) * invN - mean1 * mean1, 0.0f);
        float sc0 = __ldg(&gamma[cc])     * rsqrtf(var0 + EPSBN);
        float sc1 = __ldg(&gamma[cc + 1]) * rsqrtf(var1 + EPSBN);
        float sh0 = __ldg(&beta[cc])     - mean0 * sc0;
        float sh1 = __ldg(&beta[cc + 1]) - mean1 * sc1;
#pragma unroll
        for (int mi = 0; mi < 4; mi++) {
            int r = rA0 + mi * 16;
            float v0 = (acc[mi][ni][0] + b0v) * sc0 + sh0;
            float v1 = (acc[mi][ni][1] + b1v) * sc1 + sh1;
            float v2 = (acc[mi][ni][2] + b0v) * sc0 + sh0;
            float v3 = (acc[mi][ni][3] + b1v) * sc1 + sh1;
            *(float2*)(obase + (size_t)r * FOUT + cc)       = make_float2(v0, v1);
            *(float2*)(obase + (size_t)(r + 8) * FOUT + cc) = make_float2(v2, v3);
        }
    }
}

// ---------------------------------------------------------------------------
extern "C" void kernel_launch(void* const* d_in, const int* in_sizes, int n_in,
                              void* d_out, int out_size)
{
    const float* x     = (const float*)d_in[0];
    const float* W     = (const float*)d_in[1];
    const float* bias  = (const float*)d_in[2];
    const float* gamma = (const float*)d_in[3];
    const float* beta  = (const float*)d_in[4];
    float* out = (float*)d_out;

    cudaFuncSetAttribute(gemm_bn_kernel,
                         cudaFuncAttributeMaxDynamicSharedMemorySize,
                         SMEM_ALLOC);

    wconv_kernel<<<FOUT * FIN / 2 / 256, 256>>>(W);
    zero_stats_kernel<<<(BATCH * FOUT + 255) / 256, 256>>>();
    gemm_bn_kernel<<<BATCH * CTAS_PER_BATCH, 256, SMEM_ALLOC>>>(
        x, bias, gamma, beta, out);
}

// round 8
// speedup vs baseline: 1.2966x; 1.1467x over previous
#include <cuda_runtime.h>
#include <cuda_fp16.h>
#include <cstdint>

// Problem constants
#define BATCH 16
#define NTOK  8192
#define FIN   256
#define FOUT  256
#define EPSBN 1e-5f
#define CTAS_PER_BATCH 64        // NTOK / BM

// GEMM tiling: CTA 128x256, warp 64x64, 8 warps (2m x 4n), fp16 MMA (fp16 acc)
#define BM 128
#define BN 256
#define BK 32
#define NCHUNK (FIN / BK)        // 8
#define STAGES 3
#define LDA32 36                 // fp32 A stage row stride (floats)
#define LDKH  40                 // fp16 row stride (halves)
#define A_STAGE_BYTES (BM * LDA32 * 4)            // 18432
#define B_STAGE_BYTES (BN * LDKH * 2)             // 20480
#define STAGE_BYTES   (A_STAGE_BYTES + B_STAGE_BYTES)   // 38912
#define AH_BYTES      (BM * LDKH * 2)             // 10240
#define SMEM_ALLOC    (STAGES * STAGE_BYTES + AH_BYTES) // 126976

// device-global scratch (no allocations allowed)
__device__ __half g_Wh  [FOUT * FIN];
__device__ float  g_sum  [BATCH * FOUT];
__device__ float  g_sumsq[BATCH * FOUT];
__device__ int    g_count[BATCH];

// ---------------------------------------------------------------------------
__device__ __forceinline__ uint32_t s2u(const void* p) {
    uint32_t a;
    asm("{ .reg .u64 t; cvta.to.shared.u64 t, %1; cvt.u32.u64 %0, t; }"
        : "=r"(a) : "l"(p));
    return a;
}
__device__ __forceinline__ void cp16(uint32_t saddr, const void* g) {
    asm volatile("cp.async.cg.shared.global [%0], [%1], 16;"
                 :: "r"(saddr), "l"(g));
}
// fp16 inputs, fp16 accumulate (C/D = 2 b32 regs holding 4 halves)
__device__ __forceinline__ void mma_f16acc(uint32_t* c, const uint32_t* a,
                                           const uint32_t* b) {
    asm volatile(
        "mma.sync.aligned.m16n8k16.row.col.f16.f16.f16.f16 "
        "{%0,%1}, {%2,%3,%4,%5}, {%6,%7}, {%0,%1};"
        : "+r"(c[0]), "+r"(c[1])
        : "r"(a[0]), "r"(a[1]), "r"(a[2]), "r"(a[3]), "r"(b[0]), "r"(b[1]));
}

// ---------------------------------------------------------------------------
// Kernel A: W fp32 -> fp16 + zero stats/counters (merged, one launch)
// ---------------------------------------------------------------------------
__global__ void prep_kernel(const float* __restrict__ W) {
    int i = blockIdx.x * blockDim.x + threadIdx.x;      // 0 .. 32767
    if (i < FOUT * FIN / 2) {
        float2 f = reinterpret_cast<const float2*>(W)[i];
        reinterpret_cast<__half2*>(g_Wh)[i] = __floats2half2_rn(f.x, f.y);
    }
    if (i < BATCH * FOUT) { g_sum[i] = 0.0f; g_sumsq[i] = 0.0f; }
    if (i < BATCH) g_count[i] = 0;
}

// ---------------------------------------------------------------------------
// Kernel B: fused GEMM + BatchNorm (fp16 acc, split-K into 2 chains)
// grid = BATCH * 64 (batch = bx>>6 contiguous), block = 256
// ---------------------------------------------------------------------------
__global__ __launch_bounds__(256, 1)
void gemm_bn_kernel(const float* __restrict__ x,
                    const float* __restrict__ bias,
                    const float* __restrict__ gamma,
                    const float* __restrict__ beta,
                    float* __restrict__ out)
{
    extern __shared__ char smem[];
    const uint32_t smem_u = s2u(smem);
    __half* Ah = (__half*)(smem + STAGES * STAGE_BYTES);

    const int tid  = threadIdx.x;
    const int lane = tid & 31;
    const int wid  = tid >> 5;
    const int g    = lane >> 2;          // 0..7
    const int t    = lane & 3;           // 0..3

    const int bx = blockIdx.x;
    const int mt = bx & 63;
    const int b  = bx >> 6;
    const int m0 = mt * BM;

    const float* xb = x + ((size_t)b * NTOK + m0) * FIN;

    const int warp_m = wid >> 2;         // 0..1 -> 64-row slice
    const int warp_n = wid & 3;          // 0..3 -> 64-col slice

    // two independent fp16 accumulator chains (chunks 0-3 and 4-7)
    uint32_t accL[4][8][2], accH[4][8][2];
#pragma unroll
    for (int mi = 0; mi < 4; mi++)
#pragma unroll
        for (int ni = 0; ni < 8; ni++) {
            accL[mi][ni][0] = 0u; accL[mi][ni][1] = 0u;
            accH[mi][ni][0] = 0u; accH[mi][ni][1] = 0u;
        }

    auto load_stage = [&](int c, int s) {
        const uint32_t abase = smem_u + (uint32_t)(s * STAGE_BYTES);
        const uint32_t bbase = abase + A_STAGE_BYTES;
        const int k0 = c * BK;
#pragma unroll
        for (int i = 0; i < 4; i++) {        // A fp32: 128 rows x 8 granules
            int idx = tid + i * 256;
            int r = idx >> 3, gi = idx & 7;
            cp16(abase + (uint32_t)(r * LDA32 + gi * 4) * 4u,
                 xb + (size_t)r * FIN + k0 + gi * 4);
        }
#pragma unroll
        for (int i = 0; i < 4; i++) {        // B fp16: 256 rows x 4 granules
            int idx = tid + i * 256;
            int r = idx >> 2, gi = idx & 3;
            cp16(bbase + (uint32_t)(r * LDKH + gi * 8) * 2u,
                 g_Wh + (size_t)r * FIN + k0 + gi * 8);
        }
    };

    load_stage(0, 0);
    asm volatile("cp.async.commit_group;" ::: "memory");
    load_stage(1, 1);
    asm volatile("cp.async.commit_group;" ::: "memory");

    for (int c = 0; c < NCHUNK; c++) {
        if (c + 1 < NCHUNK)
            asm volatile("cp.async.wait_group 1;" ::: "memory");
        else
            asm volatile("cp.async.wait_group 0;" ::: "memory");
        __syncthreads();

        if (c + 2 < NCHUNK) {
            load_stage(c + 2, (c + 2) % STAGES);
            asm volatile("cp.async.commit_group;" ::: "memory");
        }

        // convert A fp32 stage -> fp16 tile
        {
            const float* Sa = (const float*)(smem + (c % STAGES) * STAGE_BYTES);
#pragma unroll
            for (int i = 0; i < 4; i++) {
                int idx = tid + i * 256;
                int r = idx >> 3, c4 = idx & 7;
                float4 v = *(const float4*)(Sa + r * LDA32 + c4 * 4);
                __half2 h0 = __floats2half2_rn(v.x, v.y);
                __half2 h1 = __floats2half2_rn(v.z, v.w);
                uint2 pk = make_uint2(*(uint32_t*)&h0, *(uint32_t*)&h1);
                *(uint2*)(Ah + r * LDKH + c4 * 4) = pk;
            }
        }
        __syncthreads();

        uint32_t (*acc)[8][2] = (c < 4) ? accL : accH;

        const __half* Aw = Ah + (warp_m * 64) * LDKH;
        const __half* Bw = (const __half*)(smem + (c % STAGES) * STAGE_BYTES
                             + A_STAGE_BYTES) + (warp_n * 64) * LDKH;
#pragma unroll
        for (int ks = 0; ks < 2; ks++) {
            const int kk = ks * 16;
            uint32_t af[4][4];
#pragma unroll
            for (int mi = 0; mi < 4; mi++) {
                int r = mi * 16 + g;
                af[mi][0] = *(const uint32_t*)&Aw[ r      * LDKH + kk + 2 * t    ];
                af[mi][1] = *(const uint32_t*)&Aw[(r + 8) * LDKH + kk + 2 * t    ];
                af[mi][2] = *(const uint32_t*)&Aw[ r      * LDKH + kk + 2 * t + 8];
                af[mi][3] = *(const uint32_t*)&Aw[(r + 8) * LDKH + kk + 2 * t + 8];
            }
            uint32_t bf[8][2];
#pragma unroll
            for (int ni = 0; ni < 8; ni++) {
                int n = ni * 8 + g;
                bf[ni][0] = *(const uint32_t*)&Bw[n * LDKH + kk + 2 * t    ];
                bf[ni][1] = *(const uint32_t*)&Bw[n * LDKH + kk + 2 * t + 8];
            }
#pragma unroll
            for (int mi = 0; mi < 4; mi++)
#pragma unroll
                for (int ni = 0; ni < 8; ni++)
                    mma_f16acc(acc[mi][ni], af[mi], bf[ni]);
        }
    }

    // ---------------- stats: column sums/sumsq -> global atomics -------------
    float* gs = &g_sum  [b * FOUT];
    float* gq = &g_sumsq[b * FOUT];
#pragma unroll
    for (int ni = 0; ni < 8; ni++) {
        const int cc = warp_n * 64 + ni * 8 + 2 * t;
        const float b0v = __ldg(&bias[cc]);
        const float b1v = __ldg(&bias[cc + 1]);
        float s0 = 0.f, s1 = 0.f, q0 = 0.f, q1 = 0.f;
#pragma unroll
        for (int mi = 0; mi < 4; mi++) {
            float2 l0 = __half22float2(*(__half2*)&accL[mi][ni][0]);
            float2 l1 = __half22float2(*(__half2*)&accL[mi][ni][1]);
            float2 h0 = __half22float2(*(__half2*)&accH[mi][ni][0]);
            float2 h1 = __half22float2(*(__half2*)&accH[mi][ni][1]);
            float v0 = l0.x + h0.x + b0v;
            float v1 = l0.y + h0.y + b1v;
            float v2 = l1.x + h1.x + b0v;
            float v3 = l1.y + h1.y + b1v;
            s0 += v0 + v2;  s1 += v1 + v3;
            q0 += v0 * v0 + v2 * v2;
            q1 += v1 * v1 + v3 * v3;
        }
#pragma unroll
        for (int m = 4; m <= 16; m <<= 1) {
            s0 += __shfl_xor_sync(0xFFFFFFFF, s0, m);
            s1 += __shfl_xor_sync(0xFFFFFFFF, s1, m);
            q0 += __shfl_xor_sync(0xFFFFFFFF, q0, m);
            q1 += __shfl_xor_sync(0xFFFFFFFF, q1, m);
        }
        if (lane < 4) {
            atomicAdd(&gs[cc], s0);  atomicAdd(&gs[cc + 1], s1);
            atomicAdd(&gq[cc], q0);  atomicAdd(&gq[cc + 1], q1);
        }
    }

    // ---------------- per-batch spin barrier ---------------------------------
    __threadfence();
    __syncthreads();
    if (tid == 0) {
        atomicAdd(&g_count[b], 1);
        while (atomicAdd(&g_count[b], 0) < CTAS_PER_BATCH)
            __nanosleep(100);
    }
    __syncthreads();
    __threadfence();

    // ---------------- normalize from registers, write final output -----------
    const float invN = 1.0f / (float)NTOK;
    float* obase = out + ((size_t)b * NTOK + m0) * FOUT;
    const int rA0 = warp_m * 64 + g;

#pragma unroll
    for (int ni = 0; ni < 8; ni++) {
        const int cc = warp_n * 64 + ni * 8 + 2 * t;
        const float b0v = __ldg(&bias[cc]);
        const float b1v = __ldg(&bias[cc + 1]);
        float mean0 = __ldcg(&gs[cc])     * invN;
        float mean1 = __ldcg(&gs[cc + 1]) * invN;
        float var0  = fmaxf(__ldcg(&gq[cc])     * invN - mean0 * mean0, 0.0f);
        float var1  = fmaxf(__ldcg(&gq[cc + 1]) * invN - mean1 * mean1, 0.0f);
        float sc0 = __ldg(&gamma[cc])     * rsqrtf(var0 + EPSBN);
        float sc1 = __ldg(&gamma[cc + 1]) * rsqrtf(var1 + EPSBN);
        float sh0 = __ldg(&beta[cc])     - mean0 * sc0;
        float sh1 = __ldg(&beta[cc + 1]) - mean1 * sc1;
#pragma unroll
        for (int mi = 0; mi < 4; mi++) {
            int r = rA0 + mi * 16;
            float2 l0 = __half22float2(*(__half2*)&accL[mi][ni][0]);
            float2 l1 = __half22float2(*(__half2*)&accL[mi][ni][1]);
            float2 h0 = __half22float2(*(__half2*)&accH[mi][ni][0]);
            float2 h1 = __half22float2(*(__half2*)&accH[mi][ni][1]);
            float v0 = (l0.x + h0.x + b0v) * sc0 + sh0;
            float v1 = (l0.y + h0.y + b1v) * sc1 + sh1;
            float v2 = (l1.x + h1.x + b0v) * sc0 + sh0;
            float v3 = (l1.y + h1.y + b1v) * sc1 + sh1;
            *(float2*)(obase + (size_t)r * FOUT + cc)       = make_float2(v0, v1);
            *(float2*)(obase + (size_t)(r + 8) * FOUT + cc) = make_float2(v2, v3);
        }
    }
}

// ---------------------------------------------------------------------------
extern "C" void kernel_launch(void* const* d_in, const int* in_sizes, int n_in,
                              void* d_out, int out_size)
{
    const float* x     = (const float*)d_in[0];
    const float* W     = (const float*)d_in[1];
    const float* bias  = (const float*)d_in[2];
    const float* gamma = (const float*)d_in[3];
    const float* beta  = (const float*)d_in[4];
    float* out = (float*)d_out;

    cudaFuncSetAttribute(gemm_bn_kernel,
                         cudaFuncAttributeMaxDynamicSharedMemorySize,
                         SMEM_ALLOC);

    prep_kernel<<<FOUT * FIN / 2 / 256, 256>>>(W);
    gemm_bn_kernel<<<BATCH * CTAS_PER_BATCH, 256, SMEM_ALLOC>>>(
        x, bias, gamma, beta, out);
}